// round 9
// baseline (speedup 1.0000x reference)
#include <cuda_runtime.h>
#include <cstdint>

// Problem constants (fixed shapes from reference)
#define B_ROWS 16384
#define T_LEN  4096
#define CHUNKS 32              // 128 elems per warp-chunk, 32 chunks per row
#define THREADS 256
#define WPB    8               // warps per block; one warp owns one full row
#define PF     4               // rolling prefetch depth (int4 loads in flight)

// Nibble of yawning bits for 4 consecutive elements (values in {0,1,2}:
// bit 1 of the value is set iff value == 2).
__device__ __forceinline__ uint32_t make_nib(int4 v)
{
    return (((uint32_t)v.x >> 1) & 1u) | ((uint32_t)v.y & 2u)
         | (((uint32_t)v.z << 1) & 4u) | (((uint32_t)v.w << 2) & 8u);
}

__global__ void __launch_bounds__(THREADS)
yawning_adjust_kernel(const float* __restrict__ drowsiness,
                      const int* __restrict__ gesture,
                      float* __restrict__ out)
{
    const int lane = threadIdx.x & 31;
    const int row  = blockIdx.x * WPB + (threadIdx.x >> 5);

    // Lane l of the warp owns elems [128c + 4l, 128c + 4l + 4) of chunk c.
    const int4* __restrict__ g4 = (const int4*)(gesture + (size_t)row * T_LEN);

    // Prologue: fill the prefetch ring (chunks 0..PF-1).
    int4 g[PF];
#pragma unroll
    for (int i = 0; i < PF; i++)
        g[i] = __ldcs(&g4[i * 32 + lane]);

    uint32_t nib_cur = make_nib(g[0]);   // nibble for chunk 0
    uint32_t carry = 0;                  // mask bit of the elem before chunk c
    int hc = 0, lc = 0;

#pragma unroll 4
    for (int c = 0; c < CHUNKS; c++) {
        // Issue the next prefetch ASAP (slot c&3 held chunk c, already
        // consumed into nib_cur at the previous iteration).
        if (c + PF < CHUNKS)
            g[c & (PF - 1)] = __ldcs(&g4[(c + PF) * 32 + lane]);

        // Nibble of chunk c+1 (needed for this chunk's boundary bits).
        uint32_t nib_next = 0;
        if (c + 1 < CHUNKS)
            nib_next = make_nib(g[(c + 1) & (PF - 1)]);

        // Cross-lane window assembly: lane l needs bits of elems
        // [e0, e0+12) where e0 = 128c + 4l  (4 own + up to 8 ahead).
        const uint32_t b0 = __shfl_sync(0xffffffffu, nib_next, 0);
        const uint32_t b1 = __shfl_sync(0xffffffffu, nib_next, 1);
        uint32_t n1 = __shfl_down_sync(0xffffffffu, nib_cur, 1);
        uint32_t n2 = __shfl_down_sync(0xffffffffu, nib_cur, 2);
        const uint32_t up = __shfl_up_sync(0xffffffffu, nib_cur, 1);
        const uint32_t newcarry =
            (__shfl_sync(0xffffffffu, nib_cur, 31) >> 3) & 1u;
        if (lane == 31) { n1 = b0; n2 = b1; }
        else if (lane == 30) { n2 = b0; }
        const uint32_t pb = (lane == 0) ? carry : ((up >> 3) & 1u);

        // Streak counting: a streak of length >= L exists iff some start
        // position (m[t] && !m[t-1]) has m[t..t+L-1] all set.
        const uint32_t ext = nib_cur | (n1 << 4) | (n2 << 8);   // 12 bits
        const uint32_t starts = nib_cur & ~((nib_cur << 1) | pb) & 0xFu;
        const uint32_t r4 = ext & (ext >> 1) & (ext >> 2) & (ext >> 3);
        const uint32_t r7 = r4  & (ext >> 4) & (ext >> 5) & (ext >> 6);
        hc += __popc(starts & r4);
        lc += __popc(starts & r7);

        carry = newcarry;
        nib_cur = nib_next;
    }

    // Warp reduction + epilogue (per-lane counts fit in 16 bits).
    int packed = hc | (lc << 16);
#pragma unroll
    for (int off = 16; off > 0; off >>= 1)
        packed += __shfl_down_sync(0xffffffffu, packed, off);

    if (lane == 0) {
        const int thc = packed & 0xffff;
        const int tlc = packed >> 16;
        float hadj = (thc >= 2) ? 0.18f * expf(-0.5f * (float)(thc - 2)) : 0.0f;
        float ladj = (tlc >= 3) ? 0.05f * expf(-0.5f * (float)(tlc - 3)) : 0.0f;
        float adj = fminf(hadj + ladj, 0.35f);
        float r = drowsiness[row] + adj;
        out[row] = fminf(fmaxf(r, 0.0f), 1.0f);
    }
}

extern "C" void kernel_launch(void* const* d_in, const int* in_sizes, int n_in,
                              void* d_out, int out_size)
{
    const float* drowsiness = (const float*)d_in[0];   // [B, 1] fp32
    const int*   gesture    = (const int*)d_in[1];     // [B, T, 1] int32
    float*       out        = (float*)d_out;           // [B, 1] fp32
    (void)in_sizes; (void)n_in; (void)out_size;

    yawning_adjust_kernel<<<B_ROWS / WPB, THREADS>>>(drowsiness, gesture, out);
}

// round 10
// speedup vs baseline: 1.0936x; 1.0936x over previous
#include <cuda_runtime.h>
#include <cstdint>

// Problem constants (fixed shapes from reference)
#define B_ROWS 16384
#define T_LEN  4096
#define WORDS  (T_LEN / 32)    // 128 mask words per row
#define CHUNKS (T_LEN / 128)   // 32 warp-chunks (128 elems each) per row
#define THREADS 512
#define RPB    2               // rows per block; warps 0-7 -> row A, 8-15 -> row B

// Spread 8 bits (positions 0..7) to positions 0,4,8,...,28.
__device__ __forceinline__ uint32_t spread4(uint32_t x)
{
    x &= 0xffu;
    x = (x | (x << 12)) & 0x000F000Fu;
    x = (x | (x << 6))  & 0x03030303u;
    x = (x | (x << 3))  & 0x11111111u;
    return x;
}

__global__ void __launch_bounds__(THREADS)
yawning_adjust_kernel(const float* __restrict__ drowsiness,
                      const int* __restrict__ gesture,
                      float* __restrict__ out)
{
    __shared__ uint32_t sball[RPB][CHUNKS * 4];  // raw interleaved ballots
    __shared__ int      sred[8];                 // 4 per row

    const int tid  = threadIdx.x;
    const int lane = tid & 31;
    const int warp = tid >> 5;                   // 0..15
    const int wsub = warp & 7;                   // warp index within its row
    const int rsel = warp >> 3;                  // 0 = row A, 1 = row B
    const int row  = blockIdx.x * RPB + rsel;

    // ── Phase 1: loads — identical per-warp pattern to the best kernel.
    // Warp covers chunks {wsub, 8+wsub, 16+wsub, 24+wsub} of ITS row only;
    // lane l loads int4 at element c*128 + l*4 (LDG.128, coalesced, stream).
    const int4* __restrict__ g4 = (const int4*)(gesture + (size_t)row * T_LEN);
    int4 g[4];
#pragma unroll
    for (int i = 0; i < 4; i++)
        g[i] = __ldcs(&g4[(i * 8 + wsub) * 32 + lane]);

    // ── Phase 2: ballot packing into this row's slot ─────────────────────
#pragma unroll
    for (int i = 0; i < 4; i++) {
        const int c = i * 8 + wsub;
        const uint32_t b0 = __ballot_sync(0xffffffffu, g[i].x == 2);
        const uint32_t b1 = __ballot_sync(0xffffffffu, g[i].y == 2);
        const uint32_t b2 = __ballot_sync(0xffffffffu, g[i].z == 2);
        const uint32_t b3 = __ballot_sync(0xffffffffu, g[i].w == 2);
        if (lane == 0) {
            sball[rsel][c * 4 + 0] = b0;
            sball[rsel][c * 4 + 1] = b1;
            sball[rsel][c * 4 + 2] = b2;
            sball[rsel][c * 4 + 3] = b3;
        }
    }
    __syncthreads();

    // ── Phase 3: per-word streak counting (threads 0..255) ───────────────
    // Thread t handles word w = t&127 of row rs = t>>7. Each thread
    // de-interleaves its own word AND the next word from the raw ballots.
    // A streak of length >= L exists iff some start (m[t] && !m[t-1]) has
    // m[t..t+L-1] all set; window <= 6 bits ahead, 1 bit behind.
    int packed = 0;   // hc | (lc << 16)
    if (tid < 2 * WORDS) {
        const int rs = tid >> 7;
        const int w  = tid & (WORDS - 1);
        const uint32_t* __restrict__ bb = sball[rs];

        uint32_t wcur = 0, wnxt = 0;
        {
            const int c = w >> 2, j = w & 3;
#pragma unroll
            for (int k = 0; k < 4; k++)
                wcur |= spread4(bb[c * 4 + k] >> (8 * j)) << k;
        }
        if (w + 1 < WORDS) {
            const int c = (w + 1) >> 2, j = (w + 1) & 3;
#pragma unroll
            for (int k = 0; k < 4; k++)
                wnxt |= spread4(bb[c * 4 + k] >> (8 * j)) << k;
        }
        uint32_t prevbit = 0;
        if (w > 0) {
            const int c = (w - 1) >> 2, j = (w - 1) & 3;
            // bit 31 of word w-1 = ballot 3, bit 8j+7
            prevbit = (bb[c * 4 + 3] >> (8 * j + 7)) & 1u;
        }

        const uint64_t ext = ((uint64_t)wnxt << 32) | (uint64_t)wcur;
        const uint32_t starts = wcur & ~((wcur << 1) | prevbit);
        const uint64_t r4 = ext & (ext >> 1) & (ext >> 2) & (ext >> 3);
        const uint64_t r7 = r4  & (ext >> 4) & (ext >> 5) & (ext >> 6);

        packed = __popc(starts & (uint32_t)r4)
               | (__popc(starts & (uint32_t)r7) << 16);
    }

    // ── Phase 4: reduction. Warps 0-3 hold row A's 128 words, 4-7 row B's.
#pragma unroll
    for (int off = 16; off > 0; off >>= 1)
        packed += __shfl_down_sync(0xffffffffu, packed, off);
    if (warp < 8 && lane == 0) sred[warp] = packed;
    __syncthreads();

    if (tid < RPB * 128 && (tid & 127) == 0) {   // tid 0 -> row A, 128 -> row B
        const int rs = tid >> 7;
        const int base = rs * 4;
        const int tot = sred[base] + sred[base + 1] + sred[base + 2] + sred[base + 3];
        const int hc = tot & 0xffff;
        const int lc = tot >> 16;

        float hadj = (hc >= 2) ? 0.18f * expf(-0.5f * (float)(hc - 2)) : 0.0f;
        float ladj = (lc >= 3) ? 0.05f * expf(-0.5f * (float)(lc - 3)) : 0.0f;
        float adj = fminf(hadj + ladj, 0.35f);
        float r = drowsiness[blockIdx.x * RPB + rs] + adj;
        out[blockIdx.x * RPB + rs] = fminf(fmaxf(r, 0.0f), 1.0f);
    }
}

extern "C" void kernel_launch(void* const* d_in, const int* in_sizes, int n_in,
                              void* d_out, int out_size)
{
    const float* drowsiness = (const float*)d_in[0];   // [B, 1] fp32
    const int*   gesture    = (const int*)d_in[1];     // [B, T, 1] int32
    float*       out        = (float*)d_out;           // [B, 1] fp32
    (void)in_sizes; (void)n_in; (void)out_size;

    yawning_adjust_kernel<<<B_ROWS / RPB, THREADS>>>(drowsiness, gesture, out);
}